// round 10
// baseline (speedup 1.0000x reference)
#include <cuda_runtime.h>
#include <cuda_bf16.h>
#include <stdint.h>
#include <math.h>

// Problem dims
#define NB   32
#define NT   512
#define ND   1024
#define NH   1024
#define NG   4096
#define MTOT (NB * NT)
#define NCTA 128
#define NTHR 512
#define HSEQ ((size_t)NB * NT * NH)

// Scratch (allocation-free rule: __device__ globals)
__device__ float g_xproj[(size_t)MTOT * NG];            // 256 MB
__device__ unsigned g_barrier;
__device__ __nv_bfloat16 g_ah[(size_t)MTOT * ND];       // x hi
__device__ __nv_bfloat16 g_al[(size_t)MTOT * ND];       // x lo
__device__ __nv_bfloat16 g_bh[(size_t)ND * NG];         // wih hi
__device__ __nv_bfloat16 g_bl[(size_t)ND * NG];         // wih lo
__device__ __nv_bfloat16 g_hh[NB * NH];                 // h hi (per step)
__device__ __nv_bfloat16 g_hl[NB * NH];                 // h lo (per step)

// mma GEMM tile config (xproj)
#define A_STRIDE 40
#define B_STRIDE 136
#define A_BUF_B (128 * A_STRIDE * 2)
#define B_BUF_B (32 * B_STRIDE * 2)
#define BUF_B   (2 * A_BUF_B + 2 * B_BUF_B)
#define GEMM_SMEM (2 * BUF_B)

// persistent-kernel smem byte offsets
//   wh/wl [1024][40] bf16 (stride 80 B = 5x16: ldmatrix-aligned, conflict-free)
//   scr   = max(2 h-buffers 2x17408, red 16x2304) = 36864
//   h buffer: hh[32][136] bf16 (stride 272 B = 17x16) then hl same
#define WH_B   0
#define WL_B   81920
#define SCR_B  163840
#define HBUF_STRIDE_B 17408
#define HROW_B 272
#define HLO_OFF 8704
#define XB_B   200704
#define GB_B   205312
#define PERSIST_SMEM 209664

// ---------------------------------------------------------------------------
// helpers
// ---------------------------------------------------------------------------
__device__ __forceinline__ unsigned ld_acq(const unsigned* p) {
    unsigned v;
    asm volatile("ld.acquire.gpu.u32 %0, [%1];" : "=r"(v) : "l"(p) : "memory");
    return v;
}

__device__ __forceinline__ float sigmoidf_(float x) {
    return 1.0f / (1.0f + __expf(-x));
}

__device__ __forceinline__ float tanh_fast(float x) {
    float a = fabsf(x);
    float e = __expf(-2.0f * a);
    float r = (1.0f - e) / (1.0f + e);
    return copysignf(r, x);
}

__device__ __forceinline__ uint32_t smem_u32(const void* p) {
    uint32_t a;
    asm("{ .reg .u64 t; cvta.to.shared.u64 t, %1; cvt.u32.u64 %0, t; }"
        : "=r"(a) : "l"(p));
    return a;
}

__device__ __forceinline__ void cpa16(uint32_t dst, const void* src) {
    asm volatile("cp.async.ca.shared.global [%0], [%1], 16;"
                 :: "r"(dst), "l"(src));
}

__device__ __forceinline__ void cpa16_cg(uint32_t dst, const void* src) {
    asm volatile("cp.async.cg.shared.global [%0], [%1], 16;"
                 :: "r"(dst), "l"(src));
}

__device__ __forceinline__ void cp_commit() {
    asm volatile("cp.async.commit_group;");
}

template <int N>
__device__ __forceinline__ void cp_wait() {
    asm volatile("cp.async.wait_group %0;" :: "n"(N));
}

__device__ __forceinline__ void ldm_x4(uint32_t* r, uint32_t addr) {
    asm volatile("ldmatrix.sync.aligned.m8n8.x4.shared.b16 {%0,%1,%2,%3}, [%4];"
                 : "=r"(r[0]), "=r"(r[1]), "=r"(r[2]), "=r"(r[3]) : "r"(addr));
}

__device__ __forceinline__ void ldm_x4_t(uint32_t* r, uint32_t addr) {
    asm volatile("ldmatrix.sync.aligned.m8n8.x4.trans.shared.b16 {%0,%1,%2,%3}, [%4];"
                 : "=r"(r[0]), "=r"(r[1]), "=r"(r[2]), "=r"(r[3]) : "r"(addr));
}

__device__ __forceinline__ void mma16816(float* d, const uint32_t* a,
                                         const uint32_t* b) {
    asm volatile(
        "mma.sync.aligned.m16n8k16.row.col.f32.bf16.bf16.f32 "
        "{%0,%1,%2,%3}, {%4,%5,%6,%7}, {%8,%9}, {%0,%1,%2,%3};"
        : "+f"(d[0]), "+f"(d[1]), "+f"(d[2]), "+f"(d[3])
        : "r"(a[0]), "r"(a[1]), "r"(a[2]), "r"(a[3]), "r"(b[0]), "r"(b[1]));
}

// ---------------------------------------------------------------------------
__global__ void init_bar_kernel() {
    if (threadIdx.x == 0) g_barrier = 0u;
}

// ---------------------------------------------------------------------------
// split x and wih into bf16 hi + bf16 residual
// ---------------------------------------------------------------------------
__global__ __launch_bounds__(256) void split_kernel(const float* __restrict__ x,
                                                    const float* __restrict__ wih) {
    size_t i = (size_t)blockIdx.x * blockDim.x + threadIdx.x;
    if (i < (size_t)MTOT * ND) {
        float a = x[i];
        __nv_bfloat16 h = __float2bfloat16(a);
        g_ah[i] = h;
        g_al[i] = __float2bfloat16(a - __bfloat162float(h));
    }
    if (i < (size_t)ND * NG) {
        float b = wih[i];
        __nv_bfloat16 h = __float2bfloat16(b);
        g_bh[i] = h;
        g_bl[i] = __float2bfloat16(b - __bfloat162float(h));
    }
}

// ---------------------------------------------------------------------------
// x_proj = x @ W_ih + bias via split-bf16 mma.sync (unchanged from R7, passing)
// ---------------------------------------------------------------------------
__device__ __forceinline__ void stage_chunk(uint32_t sbuf, int kc, int rowBase,
                                            int colBase, int tid) {
    for (int i = 0; i < 2; i++) {
        int idx = tid + i * 256;
        int row = idx >> 2;
        int c4 = idx & 3;
        size_t goff = (size_t)(rowBase + row) * ND + kc * 32 + c4 * 8;
        uint32_t d = sbuf + row * (A_STRIDE * 2) + c4 * 16;
        cpa16(d, g_ah + goff);
        cpa16(d + A_BUF_B, g_al + goff);
    }
    for (int i = 0; i < 2; i++) {
        int idx = tid + i * 256;
        int row = idx >> 4;
        int c16 = idx & 15;
        size_t goff = (size_t)(kc * 32 + row) * NG + colBase + c16 * 8;
        uint32_t d = sbuf + 2 * A_BUF_B + row * (B_STRIDE * 2) + c16 * 16;
        cpa16(d, g_bh + goff);
        cpa16(d + B_BUF_B, g_bl + goff);
    }
}

__global__ __launch_bounds__(256) void mma_xproj(const float* __restrict__ bias) {
    extern __shared__ __align__(16) char gsm[];
    const uint32_t sb0 = smem_u32(gsm);

    const int tid = threadIdx.x;
    const int lane = tid & 31;
    const int wid = tid >> 5;
    const int warp_m = wid >> 2;
    const int warp_n = wid & 3;
    const int rowBase = blockIdx.y * 128;
    const int colBase = blockIdx.x * 128;

    float acc[4][4][4];
    for (int mt = 0; mt < 4; mt++)
        for (int nt = 0; nt < 4; nt++)
            for (int r = 0; r < 4; r++)
                acc[mt][nt][r] = 0.0f;

    stage_chunk(sb0, 0, rowBase, colBase, tid);
    cp_commit();

    for (int c = 0; c < 32; c++) {
        if (c < 31) {
            stage_chunk(sb0 + ((c + 1) & 1) * BUF_B, c + 1, rowBase, colBase, tid);
            cp_commit();
            cp_wait<1>();
        } else {
            cp_wait<0>();
        }
        __syncthreads();

        const uint32_t sb = sb0 + (c & 1) * BUF_B;
        for (int ks = 0; ks < 2; ks++) {
            uint32_t ah[4][4], al[4][4], bh[2][4], bl[2][4];
            for (int mt = 0; mt < 4; mt++) {
                uint32_t ad = sb +
                    (warp_m * 64 + mt * 16 + (lane & 15)) * (A_STRIDE * 2) +
                    ks * 32 + (lane >> 4) * 16;
                ldm_x4(ah[mt], ad);
                ldm_x4(al[mt], ad + A_BUF_B);
            }
            for (int np = 0; np < 2; np++) {
                uint32_t bd = sb + 2 * A_BUF_B +
                    (ks * 16 + (lane & 15)) * (B_STRIDE * 2) +
                    (warp_n * 32 + np * 16 + (lane >> 4) * 8) * 2;
                ldm_x4_t(bh[np], bd);
                ldm_x4_t(bl[np], bd + B_BUF_B);
            }
            for (int mt = 0; mt < 4; mt++) {
                for (int np = 0; np < 2; np++) {
                    mma16816(acc[mt][2 * np],     ah[mt], &bh[np][0]);
                    mma16816(acc[mt][2 * np + 1], ah[mt], &bh[np][2]);
                    mma16816(acc[mt][2 * np],     ah[mt], &bl[np][0]);
                    mma16816(acc[mt][2 * np + 1], ah[mt], &bl[np][2]);
                    mma16816(acc[mt][2 * np],     al[mt], &bh[np][0]);
                    mma16816(acc[mt][2 * np + 1], al[mt], &bh[np][2]);
                }
            }
        }
        __syncthreads();
    }

    for (int mt = 0; mt < 4; mt++) {
        for (int nt = 0; nt < 4; nt++) {
            int row = rowBase + warp_m * 64 + mt * 16 + (lane >> 2);
            int col = colBase + warp_n * 32 + nt * 8 + (lane & 3) * 2;
            float b0 = bias[col];
            float b1 = bias[col + 1];
            float2 v0 = make_float2(acc[mt][nt][0] + b0, acc[mt][nt][1] + b1);
            float2 v1 = make_float2(acc[mt][nt][2] + b0, acc[mt][nt][3] + b1);
            *(float2*)&g_xproj[(size_t)row * NG + col] = v0;
            *(float2*)&g_xproj[(size_t)(row + 8) * NG + col] = v1;
        }
    }
}

// ---------------------------------------------------------------------------
// recurrence: stage one 128-k chunk of split h (cg = skip L1; fresh across bar)
// buffer: hh[32][136] bf16, then hl[32][136] bf16
// ---------------------------------------------------------------------------
__device__ __forceinline__ void stage_h_chunk(uint32_t hbuf, int c, int tid) {
    int row = tid >> 4;          // 0..31
    int seg = tid & 15;          // 16 segs x 8 bf16 = 128 k
    const __nv_bfloat16* srch = g_hh + row * NH + c * 128 + seg * 8;
    const __nv_bfloat16* srcl = g_hl + row * NH + c * 128 + seg * 8;
    uint32_t d = hbuf + row * HROW_B + seg * 16;
    cpa16_cg(d, srch);
    cpa16_cg(d + HLO_OFF, srcl);
}

// per-warp compute for one chunk: warp = (ks = wid&7: k16 slice, ch = wid>>3:
// col half). acc[mt 0..1][nt 0..1][4] covers 32 batches x 16 cols.
__device__ __forceinline__ void rec_compute(uint32_t hbuf, uint32_t wh,
                                            uint32_t wl, int c, int ks, int ch,
                                            int lane, float acc[2][2][4]) {
    uint32_t ahh[2][4], ahl[2][4], bh[4], bl[4];
    for (int mt = 0; mt < 2; mt++) {
        uint32_t ad = hbuf + (mt * 16 + (lane & 15)) * HROW_B +
                      ks * 32 + (lane >> 4) * 16;
        ldm_x4(ahh[mt], ad);
        ldm_x4(ahl[mt], ad + HLO_OFF);
    }
    {
        uint32_t krow = c * 128 + ks * 16 + (lane & 15);
        uint32_t coff = ch * 32 + (lane >> 4) * 16;   // bytes within 40-col row
        ldm_x4_t(bh, wh + krow * 80 + coff);
        ldm_x4_t(bl, wl + krow * 80 + coff);
    }
    for (int mt = 0; mt < 2; mt++) {
        mma16816(acc[mt][0], ahh[mt], &bh[0]);
        mma16816(acc[mt][1], ahh[mt], &bh[2]);
        mma16816(acc[mt][0], ahh[mt], &bl[0]);
        mma16816(acc[mt][1], ahh[mt], &bl[2]);
        mma16816(acc[mt][0], ahl[mt], &bh[0]);
        mma16816(acc[mt][1], ahl[mt], &bh[2]);
    }
}

// write warp partials: red[w][row 32][col 16 (+2 pad)]
__device__ __forceinline__ void write_partials(float* red, int wid, int lane,
                                               const float acc[2][2][4]) {
    float* rw = red + wid * 576;
    for (int mt = 0; mt < 2; mt++) {
        for (int nt = 0; nt < 2; nt++) {
            int row = mt * 16 + (lane >> 2);
            int col = nt * 8 + (lane & 3) * 2;
            *(float2*)&rw[row * 18 + col] =
                make_float2(acc[mt][nt][0], acc[mt][nt][1]);
            *(float2*)&rw[(row + 8) * 18 + col] =
                make_float2(acc[mt][nt][2], acc[mt][nt][3]);
        }
    }
}

// ---------------------------------------------------------------------------
// Persistent LSTM recurrence with split-bf16 tensor cores
// ---------------------------------------------------------------------------
__global__ __launch_bounds__(NTHR, 1)
void lstm_persist(const float* __restrict__ Whh, float* __restrict__ out,
                  int write_final) {
    extern __shared__ __align__(16) char smx[];
    __nv_bfloat16* wh = (__nv_bfloat16*)(smx + WH_B);
    __nv_bfloat16* wl = (__nv_bfloat16*)(smx + WL_B);
    float* red = (float*)(smx + SCR_B);
    float* xb  = (float*)(smx + XB_B);
    float* gb  = (float*)(smx + GB_B);
    const uint32_t sm0 = smem_u32(smx);
    const uint32_t wh_a = sm0 + WH_B;
    const uint32_t wl_a = sm0 + WL_B;
    const uint32_t scr_a = sm0 + SCR_B;

    const int tid = threadIdx.x;
    const int wid = tid >> 5;
    const int lane = tid & 31;
    const int base = (int)blockIdx.x * 8;
    const int ks = wid & 7;
    const int ch = wid >> 3;

    // preload + split W slice: wh/wl[k][40] (cols 0..31 used)
    for (int it = 0; it < 64; it++) {
        int idx = tid + it * NTHR;        // 0..32767
        int k = idx >> 5;
        int col = idx & 31;
        float w = Whh[(size_t)k * NG + (col >> 3) * NH + base + (col & 7)];
        __nv_bfloat16 hi = __float2bfloat16(w);
        wh[k * 40 + col] = hi;
        wl[k * 40 + col] = __float2bfloat16(w - __bfloat162float(hi));
    }

    float c_reg = 0.0f;
    unsigned bar_tgt = 0;

    __syncthreads();

    for (int t = 0; t < NT; t++) {
        // x_proj prefetch into xb[b*36 + col]
        if (tid < 256) {
            int b = tid >> 3;
            int g = (tid >> 1) & 3;
            int hf = tid & 1;
            float4 v = *(const float4*)&g_xproj[((size_t)b * NT + t) * NG +
                                                g * NH + base + hf * 4];
            *(float4*)&xb[b * 36 + g * 8 + hf * 4] = v;
        }

        float acc[2][2][4];
        for (int mt = 0; mt < 2; mt++)
            for (int nt = 0; nt < 2; nt++)
                for (int r = 0; r < 4; r++)
                    acc[mt][nt][r] = 0.0f;

        if (t > 0) {
            stage_h_chunk(scr_a, 0, tid);
            cp_commit();

            for (int c = 0; c < 8; c++) {
                if (c < 7) {
                    stage_h_chunk(scr_a + ((c + 1) & 1) * HBUF_STRIDE_B, c + 1,
                                  tid);
                    cp_commit();
                    cp_wait<1>();
                } else {
                    cp_wait<0>();
                }
                __syncthreads();
                rec_compute(scr_a + (c & 1) * HBUF_STRIDE_B, wh_a, wl_a, c,
                            ks, ch, lane, acc);
                __syncthreads();
            }
        } else {
            __syncthreads();
        }

        // partials -> red (aliases h staging; compute synced above)
        write_partials(red, wid, lane, acc);
        __syncthreads();

        // reduce 8 partials per col-half; thread (b = tid&31, cp = tid>>5)
        {
            int b = tid & 31;
            int cp = tid >> 5;               // 0..15 -> cols 2cp, 2cp+1
            int half = cp >> 3;              // col half
            float2 s = make_float2(0.0f, 0.0f);
            for (int w = 0; w < 8; w++) {
                float2 v = *(float2*)&red[(half * 8 + w) * 576 + b * 18 +
                                          ((cp * 2) & 15)];
                s.x += v.x;
                s.y += v.y;
            }
            gb[(cp * 2) * 34 + b] = s.x;
            gb[(cp * 2 + 1) * 34 + b] = s.y;
        }
        __syncthreads();

        // epilogue: thread (b, jj); c in register; write h fp32 + split bf16
        if (tid < 256) {
            const int b = tid >> 3;
            const int jj = tid & 7;
            float gate[4];
            for (int g = 0; g < 4; g++) {
                int col = g * 8 + jj;
                gate[g] = gb[col * 34 + b] + xb[b * 36 + col];
            }
            float ig = sigmoidf_(gate[0]);
            float fg = sigmoidf_(gate[1]);
            float gg = tanh_fast(gate[2]);
            float og = sigmoidf_(gate[3]);
            c_reg = fg * c_reg + ig * gg;
            float h = og * tanh_fast(c_reg);
            out[((size_t)b * NT + t) * NH + base + jj] = h;
            __nv_bfloat16 hh = __float2bfloat16(h);
            g_hh[b * NH + base + jj] = hh;
            g_hl[b * NH + base + jj] =
                __float2bfloat16(h - __bfloat162float(hh));
            if (write_final && t == NT - 1) {
                out[HSEQ + (size_t)b * NH + base + jj] = h;
                out[HSEQ + (size_t)(NB * NH) + (size_t)b * NH + base + jj] = c_reg;
            }
        }

        // grid barrier (skip after last step)
        if (t < NT - 1) {
            __threadfence();
            __syncthreads();
            bar_tgt += NCTA;
            if (tid == 0) {
                atomicAdd(&g_barrier, 1u);
                while (ld_acq(&g_barrier) < bar_tgt) { }
            }
            __syncthreads();
        }
    }
}

// ---------------------------------------------------------------------------
// launch
// ---------------------------------------------------------------------------
extern "C" void kernel_launch(void* const* d_in, const int* in_sizes, int n_in,
                              void* d_out, int out_size) {
    const float* x = (const float*)d_in[0];
    const float* wih = (const float*)d_in[1];
    const float* whh = (const float*)d_in[2];
    const float* bias = (const float*)d_in[3];
    float* out = (float*)d_out;

    (void)in_sizes;
    (void)n_in;

    cudaFuncSetAttribute(lstm_persist,
                         cudaFuncAttributeMaxDynamicSharedMemorySize,
                         PERSIST_SMEM);
    cudaFuncSetAttribute(mma_xproj,
                         cudaFuncAttributeMaxDynamicSharedMemorySize,
                         GEMM_SMEM);

    init_bar_kernel<<<1, 32>>>();

    split_kernel<<<(MTOT * ND) / 256, 256>>>(x, wih);

    dim3 grid(NG / 128, MTOT / 128);
    mma_xproj<<<grid, 256, GEMM_SMEM>>>(bias);

    int wf = (out_size >= (int)(HSEQ + 2 * NB * NH)) ? 1 : 0;
    lstm_persist<<<NCTA, NTHR, PERSIST_SMEM>>>(whh, out, wf);
}

// round 11
// speedup vs baseline: 1.1430x; 1.1430x over previous
#include <cuda_runtime.h>
#include <cuda_bf16.h>
#include <stdint.h>
#include <math.h>

// Problem dims
#define NB   32
#define NT   512
#define ND   1024
#define NH   1024
#define NG   4096
#define MTOT (NB * NT)
#define NCTA 128
#define NTHR 512
#define HSEQ ((size_t)NB * NT * NH)

// Scratch (allocation-free rule: __device__ globals)
__device__ float g_xproj[(size_t)MTOT * NG];            // 256 MB
__device__ unsigned g_barrier;
__device__ __nv_bfloat16 g_ah[(size_t)MTOT * ND];       // x hi
__device__ __nv_bfloat16 g_al[(size_t)MTOT * ND];       // x lo
__device__ __nv_bfloat16 g_bh[(size_t)ND * NG];         // wih hi
__device__ __nv_bfloat16 g_bl[(size_t)ND * NG];         // wih lo
__device__ __nv_bfloat16 g_hh[NB * NH];                 // h hi (per step)
__device__ __nv_bfloat16 g_hl[NB * NH];                 // h lo (per step)

// mma GEMM tile config (xproj) — unchanged, passing
#define A_STRIDE 40
#define B_STRIDE 136
#define A_BUF_B (128 * A_STRIDE * 2)
#define B_BUF_B (32 * B_STRIDE * 2)
#define BUF_B   (2 * A_BUF_B + 2 * B_BUF_B)
#define GEMM_SMEM (2 * BUF_B)

// persistent-kernel smem byte offsets
//   wh/wl [1024][40] bf16 (stride 80 B = 5x16: aligned, conflict-free)
//   scr: 2 h-buffers of 33792 B each (256-k chunks)
//       h buffer: hh[32][264] bf16 (row stride 528 B = 33x16) then hl same
//   red (16 x 576 fl = 36864 B) aliases scr[0..]
//   gb  (32 x 34 fl = 4352 B) at scr + 40960 (disjoint from red)
#define WH_B   0
#define WL_B   81920
#define SCR_B  163840
#define HBUF_STRIDE_B 33792
#define HROW_B 528
#define HLO_OFF 16896
#define GB_B   (SCR_B + 40960)
#define PERSIST_SMEM 231424

// ---------------------------------------------------------------------------
// helpers
// ---------------------------------------------------------------------------
__device__ __forceinline__ unsigned ld_acq(const unsigned* p) {
    unsigned v;
    asm volatile("ld.acquire.gpu.u32 %0, [%1];" : "=r"(v) : "l"(p) : "memory");
    return v;
}

__device__ __forceinline__ void red_release_add(unsigned* p, unsigned v) {
    asm volatile("red.release.gpu.global.add.u32 [%0], %1;"
                 :: "l"(p), "r"(v) : "memory");
}

__device__ __forceinline__ float sigmoidf_(float x) {
    return 1.0f / (1.0f + __expf(-x));
}

__device__ __forceinline__ float tanh_fast(float x) {
    float a = fabsf(x);
    float e = __expf(-2.0f * a);
    float r = (1.0f - e) / (1.0f + e);
    return copysignf(r, x);
}

__device__ __forceinline__ uint32_t smem_u32(const void* p) {
    uint32_t a;
    asm("{ .reg .u64 t; cvta.to.shared.u64 t, %1; cvt.u32.u64 %0, t; }"
        : "=r"(a) : "l"(p));
    return a;
}

__device__ __forceinline__ void cpa16(uint32_t dst, const void* src) {
    asm volatile("cp.async.ca.shared.global [%0], [%1], 16;"
                 :: "r"(dst), "l"(src));
}

__device__ __forceinline__ void cpa16_cg(uint32_t dst, const void* src) {
    asm volatile("cp.async.cg.shared.global [%0], [%1], 16;"
                 :: "r"(dst), "l"(src));
}

__device__ __forceinline__ void cp_commit() {
    asm volatile("cp.async.commit_group;");
}

template <int N>
__device__ __forceinline__ void cp_wait() {
    asm volatile("cp.async.wait_group %0;" :: "n"(N));
}

__device__ __forceinline__ void ldm_x4(uint32_t* r, uint32_t addr) {
    asm volatile("ldmatrix.sync.aligned.m8n8.x4.shared.b16 {%0,%1,%2,%3}, [%4];"
                 : "=r"(r[0]), "=r"(r[1]), "=r"(r[2]), "=r"(r[3]) : "r"(addr));
}

__device__ __forceinline__ void ldm_x4_t(uint32_t* r, uint32_t addr) {
    asm volatile("ldmatrix.sync.aligned.m8n8.x4.trans.shared.b16 {%0,%1,%2,%3}, [%4];"
                 : "=r"(r[0]), "=r"(r[1]), "=r"(r[2]), "=r"(r[3]) : "r"(addr));
}

__device__ __forceinline__ void mma16816(float* d, const uint32_t* a,
                                         const uint32_t* b) {
    asm volatile(
        "mma.sync.aligned.m16n8k16.row.col.f32.bf16.bf16.f32 "
        "{%0,%1,%2,%3}, {%4,%5,%6,%7}, {%8,%9}, {%0,%1,%2,%3};"
        : "+f"(d[0]), "+f"(d[1]), "+f"(d[2]), "+f"(d[3])
        : "r"(a[0]), "r"(a[1]), "r"(a[2]), "r"(a[3]), "r"(b[0]), "r"(b[1]));
}

// ---------------------------------------------------------------------------
__global__ void init_bar_kernel() {
    if (threadIdx.x == 0) g_barrier = 0u;
}

// ---------------------------------------------------------------------------
// split x and wih into bf16 hi + bf16 residual
// ---------------------------------------------------------------------------
__global__ __launch_bounds__(256) void split_kernel(const float* __restrict__ x,
                                                    const float* __restrict__ wih) {
    size_t i = (size_t)blockIdx.x * blockDim.x + threadIdx.x;
    if (i < (size_t)MTOT * ND) {
        float a = x[i];
        __nv_bfloat16 h = __float2bfloat16(a);
        g_ah[i] = h;
        g_al[i] = __float2bfloat16(a - __bfloat162float(h));
    }
    if (i < (size_t)ND * NG) {
        float b = wih[i];
        __nv_bfloat16 h = __float2bfloat16(b);
        g_bh[i] = h;
        g_bl[i] = __float2bfloat16(b - __bfloat162float(h));
    }
}

// ---------------------------------------------------------------------------
// x_proj = x @ W_ih + bias via split-bf16 mma.sync (unchanged from R7, passing)
// ---------------------------------------------------------------------------
__device__ __forceinline__ void stage_chunk(uint32_t sbuf, int kc, int rowBase,
                                            int colBase, int tid) {
    for (int i = 0; i < 2; i++) {
        int idx = tid + i * 256;
        int row = idx >> 2;
        int c4 = idx & 3;
        size_t goff = (size_t)(rowBase + row) * ND + kc * 32 + c4 * 8;
        uint32_t d = sbuf + row * (A_STRIDE * 2) + c4 * 16;
        cpa16(d, g_ah + goff);
        cpa16(d + A_BUF_B, g_al + goff);
    }
    for (int i = 0; i < 2; i++) {
        int idx = tid + i * 256;
        int row = idx >> 4;
        int c16 = idx & 15;
        size_t goff = (size_t)(kc * 32 + row) * NG + colBase + c16 * 8;
        uint32_t d = sbuf + 2 * A_BUF_B + row * (B_STRIDE * 2) + c16 * 16;
        cpa16(d, g_bh + goff);
        cpa16(d + B_BUF_B, g_bl + goff);
    }
}

__global__ __launch_bounds__(256) void mma_xproj(const float* __restrict__ bias) {
    extern __shared__ __align__(16) char gsm[];
    const uint32_t sb0 = smem_u32(gsm);

    const int tid = threadIdx.x;
    const int lane = tid & 31;
    const int wid = tid >> 5;
    const int warp_m = wid >> 2;
    const int warp_n = wid & 3;
    const int rowBase = blockIdx.y * 128;
    const int colBase = blockIdx.x * 128;

    float acc[4][4][4];
    for (int mt = 0; mt < 4; mt++)
        for (int nt = 0; nt < 4; nt++)
            for (int r = 0; r < 4; r++)
                acc[mt][nt][r] = 0.0f;

    stage_chunk(sb0, 0, rowBase, colBase, tid);
    cp_commit();

    for (int c = 0; c < 32; c++) {
        if (c < 31) {
            stage_chunk(sb0 + ((c + 1) & 1) * BUF_B, c + 1, rowBase, colBase, tid);
            cp_commit();
            cp_wait<1>();
        } else {
            cp_wait<0>();
        }
        __syncthreads();

        const uint32_t sb = sb0 + (c & 1) * BUF_B;
        for (int ks = 0; ks < 2; ks++) {
            uint32_t ah[4][4], al[4][4], bh[2][4], bl[2][4];
            for (int mt = 0; mt < 4; mt++) {
                uint32_t ad = sb +
                    (warp_m * 64 + mt * 16 + (lane & 15)) * (A_STRIDE * 2) +
                    ks * 32 + (lane >> 4) * 16;
                ldm_x4(ah[mt], ad);
                ldm_x4(al[mt], ad + A_BUF_B);
            }
            for (int np = 0; np < 2; np++) {
                uint32_t bd = sb + 2 * A_BUF_B +
                    (ks * 16 + (lane & 15)) * (B_STRIDE * 2) +
                    (warp_n * 32 + np * 16 + (lane >> 4) * 8) * 2;
                ldm_x4_t(bh[np], bd);
                ldm_x4_t(bl[np], bd + B_BUF_B);
            }
            for (int mt = 0; mt < 4; mt++) {
                for (int np = 0; np < 2; np++) {
                    mma16816(acc[mt][2 * np],     ah[mt], &bh[np][0]);
                    mma16816(acc[mt][2 * np + 1], ah[mt], &bh[np][2]);
                    mma16816(acc[mt][2 * np],     ah[mt], &bl[np][0]);
                    mma16816(acc[mt][2 * np + 1], ah[mt], &bl[np][2]);
                    mma16816(acc[mt][2 * np],     al[mt], &bh[np][0]);
                    mma16816(acc[mt][2 * np + 1], al[mt], &bh[np][2]);
                }
            }
        }
        __syncthreads();
    }

    for (int mt = 0; mt < 4; mt++) {
        for (int nt = 0; nt < 4; nt++) {
            int row = rowBase + warp_m * 64 + mt * 16 + (lane >> 2);
            int col = colBase + warp_n * 32 + nt * 8 + (lane & 3) * 2;
            float b0 = bias[col];
            float b1 = bias[col + 1];
            float2 v0 = make_float2(acc[mt][nt][0] + b0, acc[mt][nt][1] + b1);
            float2 v1 = make_float2(acc[mt][nt][2] + b0, acc[mt][nt][3] + b1);
            *(float2*)&g_xproj[(size_t)row * NG + col] = v0;
            *(float2*)&g_xproj[(size_t)(row + 8) * NG + col] = v1;
        }
    }
}

// ---------------------------------------------------------------------------
// recurrence: stage one 256-k chunk of split h (cg = skip L1; fresh across bar)
// buffer: hh[32][264] bf16 (row 528 B), then hl same at +16896
// ---------------------------------------------------------------------------
__device__ __forceinline__ void stage_h_chunk(uint32_t hbuf, int c, int tid) {
    int row = tid >> 4;          // 0..31
    int seg = tid & 15;          // 2 x 16B segs per thread per half
    const __nv_bfloat16* srch = g_hh + row * NH + c * 256 + seg * 8;
    const __nv_bfloat16* srcl = g_hl + row * NH + c * 256 + seg * 8;
    uint32_t d = hbuf + row * HROW_B + seg * 16;
    cpa16_cg(d, srch);
    cpa16_cg(d + 256, srch + 128);
    cpa16_cg(d + HLO_OFF, srcl);
    cpa16_cg(d + HLO_OFF + 256, srcl + 128);
}

// per-warp compute for one 256-k chunk: warp = (ks 0..7: k32 slice,
// ch 0..1: col half). Inner loop over 2 k16 sub-slices.
__device__ __forceinline__ void rec_compute(uint32_t hbuf, uint32_t wh,
                                            uint32_t wl, int c, int ks, int ch,
                                            int lane, float acc[2][2][4]) {
    for (int sub = 0; sub < 2; sub++) {
        uint32_t ahh[2][4], ahl[2][4], bh[4], bl[4];
        for (int mt = 0; mt < 2; mt++) {
            uint32_t ad = hbuf + (mt * 16 + (lane & 15)) * HROW_B +
                          ks * 64 + sub * 32 + (lane >> 4) * 16;
            ldm_x4(ahh[mt], ad);
            ldm_x4(ahl[mt], ad + HLO_OFF);
        }
        {
            uint32_t krow = c * 256 + ks * 32 + sub * 16 + (lane & 15);
            uint32_t coff = ch * 32 + (lane >> 4) * 16;
            ldm_x4_t(bh, wh + krow * 80 + coff);
            ldm_x4_t(bl, wl + krow * 80 + coff);
        }
        for (int mt = 0; mt < 2; mt++) {
            mma16816(acc[mt][0], ahh[mt], &bh[0]);
            mma16816(acc[mt][1], ahh[mt], &bh[2]);
            mma16816(acc[mt][0], ahh[mt], &bl[0]);
            mma16816(acc[mt][1], ahh[mt], &bl[2]);
            mma16816(acc[mt][0], ahl[mt], &bh[0]);
            mma16816(acc[mt][1], ahl[mt], &bh[2]);
        }
    }
}

// write warp partials: red[w][row 32][col 16 (+2 pad)]
__device__ __forceinline__ void write_partials(float* red, int wid, int lane,
                                               const float acc[2][2][4]) {
    float* rw = red + wid * 576;
    for (int mt = 0; mt < 2; mt++) {
        for (int nt = 0; nt < 2; nt++) {
            int row = mt * 16 + (lane >> 2);
            int col = nt * 8 + (lane & 3) * 2;
            *(float2*)&rw[row * 18 + col] =
                make_float2(acc[mt][nt][0], acc[mt][nt][1]);
            *(float2*)&rw[(row + 8) * 18 + col] =
                make_float2(acc[mt][nt][2], acc[mt][nt][3]);
        }
    }
}

// ---------------------------------------------------------------------------
// Persistent LSTM recurrence with split-bf16 tensor cores
// ---------------------------------------------------------------------------
__global__ __launch_bounds__(NTHR, 1)
void lstm_persist(const float* __restrict__ Whh, float* __restrict__ out,
                  int write_final) {
    extern __shared__ __align__(16) char smx[];
    __nv_bfloat16* wh = (__nv_bfloat16*)(smx + WH_B);
    __nv_bfloat16* wl = (__nv_bfloat16*)(smx + WL_B);
    float* red = (float*)(smx + SCR_B);
    float* gb  = (float*)(smx + GB_B);
    const uint32_t sm0 = smem_u32(smx);
    const uint32_t wh_a = sm0 + WH_B;
    const uint32_t wl_a = sm0 + WL_B;
    const uint32_t scr_a = sm0 + SCR_B;

    const int tid = threadIdx.x;
    const int wid = tid >> 5;
    const int lane = tid & 31;
    const int base = (int)blockIdx.x * 8;
    const int ks = wid & 7;
    const int ch = wid >> 3;

    // preload + split W slice: wh/wl[k][40] (cols 0..31 used)
    for (int it = 0; it < 64; it++) {
        int idx = tid + it * NTHR;        // 0..32767
        int k = idx >> 5;
        int col = idx & 31;
        float w = Whh[(size_t)k * NG + (col >> 3) * NH + base + (col & 7)];
        __nv_bfloat16 hi = __float2bfloat16(w);
        wh[k * 40 + col] = hi;
        wl[k * 40 + col] = __float2bfloat16(w - __bfloat162float(hi));
    }

    float c_reg = 0.0f;
    unsigned bar_tgt = 0;

    __syncthreads();

    for (int t = 0; t < NT; t++) {
        // x_proj prefetch into registers (epilogue threads only)
        float xg[4];
        if (tid < 256) {
            int b = tid >> 3;
            int jj = tid & 7;
            const float* xp = g_xproj + ((size_t)b * NT + t) * NG + base + jj;
            xg[0] = xp[0];
            xg[1] = xp[NH];
            xg[2] = xp[2 * NH];
            xg[3] = xp[3 * NH];
        }

        float acc[2][2][4];
        for (int mt = 0; mt < 2; mt++)
            for (int nt = 0; nt < 2; nt++)
                for (int r = 0; r < 4; r++)
                    acc[mt][nt][r] = 0.0f;

        if (t > 0) {
            stage_h_chunk(scr_a, 0, tid);
            cp_commit();

            for (int c = 0; c < 4; c++) {
                if (c < 3) {
                    stage_h_chunk(scr_a + ((c + 1) & 1) * HBUF_STRIDE_B, c + 1,
                                  tid);
                    cp_commit();
                    cp_wait<1>();
                } else {
                    cp_wait<0>();
                }
                __syncthreads();
                rec_compute(scr_a + (c & 1) * HBUF_STRIDE_B, wh_a, wl_a, c,
                            ks, ch, lane, acc);
                __syncthreads();
            }
        }

        // partials -> red (red aliases h buffer 0; its compute is done)
        write_partials(red, wid, lane, acc);
        __syncthreads();

        // reduce 8 partials per col-half; thread (b = tid&31, cp = tid>>5)
        {
            int b = tid & 31;
            int cp = tid >> 5;               // 0..15 -> cols 2cp, 2cp+1
            int half = cp >> 3;
            float2 s = make_float2(0.0f, 0.0f);
            for (int w = 0; w < 8; w++) {
                float2 v = *(float2*)&red[(half * 8 + w) * 576 + b * 18 +
                                          ((cp * 2) & 15)];
                s.x += v.x;
                s.y += v.y;
            }
            gb[(cp * 2) * 34 + b] = s.x;
            gb[(cp * 2 + 1) * 34 + b] = s.y;
        }
        __syncthreads();

        // epilogue: thread (b, jj); c in register; write h fp32 + split bf16
        if (tid < 256) {
            const int b = tid >> 3;
            const int jj = tid & 7;
            float gate[4];
            for (int g = 0; g < 4; g++) {
                gate[g] = gb[(g * 8 + jj) * 34 + b] + xg[g];
            }
            float ig = sigmoidf_(gate[0]);
            float fg = sigmoidf_(gate[1]);
            float gg = tanh_fast(gate[2]);
            float og = sigmoidf_(gate[3]);
            c_reg = fg * c_reg + ig * gg;
            float h = og * tanh_fast(c_reg);
            out[((size_t)b * NT + t) * NH + base + jj] = h;
            __nv_bfloat16 hh = __float2bfloat16(h);
            g_hh[b * NH + base + jj] = hh;
            g_hl[b * NH + base + jj] =
                __float2bfloat16(h - __bfloat162float(hh));
            if (write_final && t == NT - 1) {
                out[HSEQ + (size_t)b * NH + base + jj] = h;
                out[HSEQ + (size_t)(NB * NH) + (size_t)b * NH + base + jj] = c_reg;
            }
        }

        // grid barrier (release/acquire; skip after last step)
        if (t < NT - 1) {
            __syncthreads();
            bar_tgt += NCTA;
            if (tid == 0) {
                red_release_add(&g_barrier, 1u);
                while (ld_acq(&g_barrier) < bar_tgt) { }
            }
            __syncthreads();
        }
    }
}

// ---------------------------------------------------------------------------
// launch
// ---------------------------------------------------------------------------
extern "C" void kernel_launch(void* const* d_in, const int* in_sizes, int n_in,
                              void* d_out, int out_size) {
    const float* x = (const float*)d_in[0];
    const float* wih = (const float*)d_in[1];
    const float* whh = (const float*)d_in[2];
    const float* bias = (const float*)d_in[3];
    float* out = (float*)d_out;

    (void)in_sizes;
    (void)n_in;

    cudaFuncSetAttribute(lstm_persist,
                         cudaFuncAttributeMaxDynamicSharedMemorySize,
                         PERSIST_SMEM);
    cudaFuncSetAttribute(mma_xproj,
                         cudaFuncAttributeMaxDynamicSharedMemorySize,
                         GEMM_SMEM);

    init_bar_kernel<<<1, 32>>>();

    split_kernel<<<(MTOT * ND) / 256, 256>>>(x, wih);

    dim3 grid(NG / 128, MTOT / 128);
    mma_xproj<<<grid, 256, GEMM_SMEM>>>(bias);

    int wf = (out_size >= (int)(HSEQ + 2 * NB * NH)) ? 1 : 0;
    lstm_persist<<<NCTA, NTHR, PERSIST_SMEM>>>(whh, out, wf);
}